// round 8
// baseline (speedup 1.0000x reference)
#include <cuda_runtime.h>
#include <cuda_bf16.h>

// FrequencyAdaptiveNormSimple: out = sum_w softmax(alpha)[h,w] * (x - mu_w)/max(sd_w,1e-4)
// windows (5,10,20), replicate-padded stats for t < w-1. B=32,T=2048,H=512 fp32.
// Scalar register-ring kernel; TCc=128 for grid-level occupancy; scaled-weight
// normalization (sqrt(W-1) folded into alpha) for a shorter fma chain.

constexpr int Bc  = 32;
constexpr int Tc  = 2048;
constexpr int Hc  = 512;
constexpr int HCc = 128;          // h per block (= threads per block)
constexpr int TCc = 128;          // time chunk per block
constexpr int NCH = Tc / TCc;     // 16
constexpr int NHB = Hc / HCc;     // 4
static_assert(TCc % 20 == 8 && (TCc - 20) % 20 == 8, "tail length assumed 8");

static __device__ __forceinline__ float rsq(float v) {
    float r;
    asm("rsqrt.approx.f32 %0, %1;" : "=f"(r) : "f"(v));
    return r;
}

// edge-path znorm (t < 20), plain form
template <int W>
static __device__ __forceinline__ float zc(float xv, float s, float q, float al) {
    const float c1   = 1.0f / (float)(W - 1);
    const float c2   = 1.0f / ((float)W * (float)(W - 1));
    const float invW = 1.0f / (float)W;
    float var   = q * c1 - (s * c2) * s;
    float invsd = rsq(fmaxf(var, 1e-8f));
    return (xv - s * invW) * (al * invsd);
}

// steady-state znorm with pre-scaled weight alS = al*sqrt(W-1):
//   var0 = q - s^2/W  (= (W-1)*var), clamp at (W-1)*1e-8
//   contribution = (v - s/W) * alS * rsqrt(var0)
template <int W>
static __device__ __forceinline__ float wz(float v, float s, float q, float alS) {
    const float nIW  = -1.0f / (float)W;
    const float epsW = (float)(W - 1) * 1e-8f;
    float t    = s * nIW;
    float m    = fmaf(s, nIW, v);
    float var0 = fmaf(t, s, q);
    float w    = alS * rsq(fmaxf(var0, epsW));
    return m * w;
}

// one steady-state timestep; J literal so ring indices are compile-time
#define STEP(J, V, OPTR) {                                   \
    float _v   = (V);                                        \
    float _v2  = _v * _v;                                    \
    float _l20 = r[(J)];                                     \
    float _l10 = r[((J) + 10) % 20];                         \
    float _l5  = r[((J) + 15) % 20];                         \
    s20 += _v - _l20;  q20 = fmaf(-_l20, _l20, q20 + _v2);   \
    s10 += _v - _l10;  q10 = fmaf(-_l10, _l10, q10 + _v2);   \
    s5  += _v - _l5;   q5  = fmaf(-_l5,  _l5,  q5  + _v2);   \
    r[(J)] = _v;                                             \
    float _o = wz<5>(_v, s5, q5, a5)                         \
             + wz<10>(_v, s10, q10, a10)                     \
             + wz<20>(_v, s20, q20, a20);                    \
    __stcs(&(OPTR)[(J) * Hc], _o); }

__global__ __launch_bounds__(HCc, 8)
void fan_kernel(const float* __restrict__ x,
                const float* __restrict__ alpha,
                float* __restrict__ out)
{
    const int tid   = threadIdx.x;
    int blk         = blockIdx.x;
    const int chunk = blk % NCH; blk /= NCH;
    const int hb    = blk % NHB; blk /= NHB;
    const int b     = blk;
    const int h     = hb * HCc + tid;

    const float* xp = x   + (size_t)b * Tc * Hc + h;
    float*       op = out + (size_t)b * Tc * Hc + h;

    // per-feature softmax over 3 window weights
    float a0 = __ldg(&alpha[h * 3 + 0]);
    float a1 = __ldg(&alpha[h * 3 + 1]);
    float a2 = __ldg(&alpha[h * 3 + 2]);
    float mx = fmaxf(a0, fmaxf(a1, a2));
    float e0 = __expf(a0 - mx), e1 = __expf(a1 - mx), e2 = __expf(a2 - mx);
    float ai = 1.0f / (e0 + e1 + e2);
    const float al5 = e0 * ai, al10 = e1 * ai, al20 = e2 * ai;
    // pre-scaled weights for steady state
    const float a5  = al5  * 2.0f;            // sqrt(4)
    const float a10 = al10 * 3.0f;            // sqrt(9)
    const float a20 = al20 * 4.35889894354f;  // sqrt(19)

    float r[20];                 // register ring: last 20 x values
    float s5, q5, s10, q10, s20, q20;
    int tbeg;

    if (chunk == 0) {
        // ---- t = 0..19 with replicate-padded leading stats ----
        float ob[20];
        #pragma unroll
        for (int t = 0; t < 20; t++) { r[t] = __ldg(&xp[t * Hc]); ob[t] = 0.0f; }

        // w = 5
        {
            float s = 0.f, q = 0.f;
            #pragma unroll
            for (int t = 0; t < 20; t++) {
                float v = r[t];
                s += v; q += v * v;
                if (t >= 5) { float l = r[t - 5]; s -= l; q -= l * l; }
                if (t == 4) {
                    #pragma unroll
                    for (int tp = 0; tp <= 4; tp++) ob[tp] += zc<5>(r[tp], s, q, al5);
                } else if (t > 4) {
                    ob[t] += zc<5>(v, s, q, al5);
                }
            }
        }
        // w = 10
        {
            float s = 0.f, q = 0.f;
            #pragma unroll
            for (int t = 0; t < 20; t++) {
                float v = r[t];
                s += v; q += v * v;
                if (t >= 10) { float l = r[t - 10]; s -= l; q -= l * l; }
                if (t == 9) {
                    #pragma unroll
                    for (int tp = 0; tp <= 9; tp++) ob[tp] += zc<10>(r[tp], s, q, al10);
                } else if (t > 9) {
                    ob[t] += zc<10>(v, s, q, al10);
                }
            }
        }
        // w = 20
        {
            float s = 0.f, q = 0.f;
            #pragma unroll
            for (int t = 0; t < 20; t++) { float v = r[t]; s += v; q += v * v; }
            #pragma unroll
            for (int tp = 0; tp < 20; tp++) ob[tp] += zc<20>(r[tp], s, q, al20);
        }
        #pragma unroll
        for (int t = 0; t < 20; t++) __stcs(&op[t * Hc], ob[t]);

        // prefix sums for steady state (ring holds x[0..19])
        s5 = q5 = s10 = q10 = s20 = q20 = 0.f;
        #pragma unroll
        for (int i = 0; i < 20; i++) {
            float v = r[i], v2 = v * v;
            s20 += v; q20 += v2;
            if (i >= 10) { s10 += v; q10 += v2; }
            if (i >= 15) { s5  += v; q5  += v2; }
        }
        tbeg = 20;
    } else {
        // ---- halo warmup: ring <- x[t0-20 .. t0-1] ----
        const int t0 = chunk * TCc;
        const float* ph = xp + (size_t)(t0 - 20) * Hc;
        #pragma unroll
        for (int i = 0; i < 20; i++) r[i] = __ldg(&ph[i * Hc]);
        s5 = q5 = s10 = q10 = s20 = q20 = 0.f;
        #pragma unroll
        for (int i = 0; i < 20; i++) {
            float v = r[i], v2 = v * v;
            s20 += v; q20 += v2;
            if (i >= 10) { s10 += v; q10 += v2; }
            if (i >= 15) { s5  += v; q5  += v2; }
        }
        tbeg = t0;
    }

    const int tend = chunk * TCc + TCc;
    int tb = tbeg;

    // ---- steady state: 20-step blocks, compile-time ring indices ----
    for (; tb + 20 <= tend; tb += 20) {
        const float* p = xp + (size_t)tb * Hc;
        float*       o = op + (size_t)tb * Hc;
        float xv[10];
        #pragma unroll
        for (int j = 0; j < 10; j++) xv[j] = __ldg(&p[j * Hc]);
        STEP(0, xv[0], o); STEP(1, xv[1], o); STEP(2, xv[2], o); STEP(3, xv[3], o);
        STEP(4, xv[4], o); STEP(5, xv[5], o); STEP(6, xv[6], o); STEP(7, xv[7], o);
        STEP(8, xv[8], o); STEP(9, xv[9], o);
        #pragma unroll
        for (int j = 0; j < 10; j++) xv[j] = __ldg(&p[(j + 10) * Hc]);
        STEP(10, xv[0], o); STEP(11, xv[1], o); STEP(12, xv[2], o); STEP(13, xv[3], o);
        STEP(14, xv[4], o); STEP(15, xv[5], o); STEP(16, xv[6], o); STEP(17, xv[7], o);
        STEP(18, xv[8], o); STEP(19, xv[9], o);
    }

    // ---- fixed 8-step tail (ring base slot is 0 here) ----
    {
        const float* p = xp + (size_t)tb * Hc;
        float*       o = op + (size_t)tb * Hc;
        float xv[8];
        #pragma unroll
        for (int j = 0; j < 8; j++) xv[j] = __ldg(&p[j * Hc]);
        STEP(0, xv[0], o); STEP(1, xv[1], o); STEP(2, xv[2], o); STEP(3, xv[3], o);
        STEP(4, xv[4], o); STEP(5, xv[5], o); STEP(6, xv[6], o); STEP(7, xv[7], o);
    }
}

extern "C" void kernel_launch(void* const* d_in, const int* in_sizes, int n_in,
                              void* d_out, int out_size) {
    const float* x     = (const float*)d_in[0];
    const float* alpha = (const float*)d_in[1];
    float*       out   = (float*)d_out;
    dim3 grid(Bc * NHB * NCH);   // 32 * 4 * 16 = 2048 blocks
    dim3 block(HCc);             // 128 threads
    fan_kernel<<<grid, block>>>(x, alpha, out);
}

// round 9
// speedup vs baseline: 1.2184x; 1.2184x over previous
#include <cuda_runtime.h>
#include <cuda_bf16.h>

// FrequencyAdaptiveNormSimple: out = sum_w softmax(alpha)[h,w] * (x - mu_w)/max(sd_w,1e-4)
// windows (5,10,20), replicate-padded stats for t < w-1. B=32,T=2048,H=512 fp32.
// Register-ring kernel, R4 structure. 64-thread blocks, TCc=128 for occupancy
// (8192 warps), NO forced min-blocks (avoid hot-loop spills seen in R8).

constexpr int Bc  = 32;
constexpr int Tc  = 2048;
constexpr int Hc  = 512;
constexpr int HCc = 64;           // h per block (= threads per block)
constexpr int TCc = 128;          // time chunk per block
constexpr int NCH = Tc / TCc;     // 16
constexpr int NHB = Hc / HCc;     // 8
static_assert(TCc % 20 == 8, "tail length assumed 8");

static __device__ __forceinline__ float rsq(float v) {
    float r;
    asm("rsqrt.approx.f32 %0, %1;" : "=f"(r) : "f"(v));
    return r;
}

// edge-path znorm (t < 20), plain form
template <int W>
static __device__ __forceinline__ float zc(float xv, float s, float q, float al) {
    const float c1   = 1.0f / (float)(W - 1);
    const float c2   = 1.0f / ((float)W * (float)(W - 1));
    const float invW = 1.0f / (float)W;
    float var   = q * c1 - (s * c2) * s;
    float invsd = rsq(fmaxf(var, 1e-8f));
    return (xv - s * invW) * (al * invsd);
}

// steady-state znorm pieces with pre-scaled weight alS = al*sqrt(W-1):
//   var0 = q - s^2/W  (= (W-1)*var), clamped at (W-1)*1e-8
//   m = v - s/W ;  w = alS * rsqrt(var0) ;  contribution = m*w
template <int W>
static __device__ __forceinline__ void wz(float v, float s, float q, float alS,
                                          float& m, float& w) {
    const float nIW  = -1.0f / (float)W;
    const float epsW = (float)(W - 1) * 1e-8f;
    float t    = s * nIW;
    m          = fmaf(s, nIW, v);
    float var0 = fmaf(t, s, q);
    w          = alS * rsq(fmaxf(var0, epsW));
}

// one steady-state timestep; J literal so ring indices are compile-time
#define STEP(J, V, OPTR) {                                   \
    float _v   = (V);                                        \
    float _v2  = _v * _v;                                    \
    float _l20 = r[(J)];                                     \
    float _l10 = r[((J) + 10) % 20];                         \
    float _l5  = r[((J) + 15) % 20];                         \
    s20 += _v - _l20;  q20 += _v2 - _l20 * _l20;             \
    s10 += _v - _l10;  q10 += _v2 - _l10 * _l10;             \
    s5  += _v - _l5;   q5  += _v2 - _l5  * _l5;              \
    r[(J)] = _v;                                             \
    float _m5, _w5, _m10, _w10, _m20, _w20;                  \
    wz<5>(_v, s5, q5, a5, _m5, _w5);                         \
    wz<10>(_v, s10, q10, a10, _m10, _w10);                   \
    wz<20>(_v, s20, q20, a20, _m20, _w20);                   \
    float _o = fmaf(_m5, _w5, fmaf(_m10, _w10, _m20 * _w20));\
    __stcs(&(OPTR)[(J) * Hc], _o); }

__global__ __launch_bounds__(HCc)
void fan_kernel(const float* __restrict__ x,
                const float* __restrict__ alpha,
                float* __restrict__ out)
{
    const int tid   = threadIdx.x;
    int blk         = blockIdx.x;
    const int chunk = blk % NCH; blk /= NCH;
    const int hb    = blk % NHB; blk /= NHB;
    const int b     = blk;
    const int h     = hb * HCc + tid;

    const float* xp = x   + (size_t)b * Tc * Hc + h;
    float*       op = out + (size_t)b * Tc * Hc + h;

    // per-feature softmax over 3 window weights
    float a0 = __ldg(&alpha[h * 3 + 0]);
    float a1 = __ldg(&alpha[h * 3 + 1]);
    float a2 = __ldg(&alpha[h * 3 + 2]);
    float mx = fmaxf(a0, fmaxf(a1, a2));
    float e0 = __expf(a0 - mx), e1 = __expf(a1 - mx), e2 = __expf(a2 - mx);
    float ai = 1.0f / (e0 + e1 + e2);
    const float al5 = e0 * ai, al10 = e1 * ai, al20 = e2 * ai;
    // pre-scaled weights for steady state (sqrt(W-1) folded in)
    const float a5  = al5  * 2.0f;            // sqrt(4)
    const float a10 = al10 * 3.0f;            // sqrt(9)
    const float a20 = al20 * 4.35889894354f;  // sqrt(19)

    float r[20];                 // register ring: last 20 x values
    float s5, q5, s10, q10, s20, q20;
    int tbeg;

    if (chunk == 0) {
        // ---- t = 0..19 with replicate-padded leading stats ----
        float ob[20];
        #pragma unroll
        for (int t = 0; t < 20; t++) { r[t] = __ldg(&xp[t * Hc]); ob[t] = 0.0f; }

        // w = 5
        {
            float s = 0.f, q = 0.f;
            #pragma unroll
            for (int t = 0; t < 20; t++) {
                float v = r[t];
                s += v; q += v * v;
                if (t >= 5) { float l = r[t - 5]; s -= l; q -= l * l; }
                if (t == 4) {
                    #pragma unroll
                    for (int tp = 0; tp <= 4; tp++) ob[tp] += zc<5>(r[tp], s, q, al5);
                } else if (t > 4) {
                    ob[t] += zc<5>(v, s, q, al5);
                }
            }
            s5 = s; q5 = q;
        }
        // w = 10
        {
            float s = 0.f, q = 0.f;
            #pragma unroll
            for (int t = 0; t < 20; t++) {
                float v = r[t];
                s += v; q += v * v;
                if (t >= 10) { float l = r[t - 10]; s -= l; q -= l * l; }
                if (t == 9) {
                    #pragma unroll
                    for (int tp = 0; tp <= 9; tp++) ob[tp] += zc<10>(r[tp], s, q, al10);
                } else if (t > 9) {
                    ob[t] += zc<10>(v, s, q, al10);
                }
            }
            s10 = s; q10 = q;
        }
        // w = 20
        {
            float s = 0.f, q = 0.f;
            #pragma unroll
            for (int t = 0; t < 20; t++) { float v = r[t]; s += v; q += v * v; }
            #pragma unroll
            for (int tp = 0; tp < 20; tp++) ob[tp] += zc<20>(r[tp], s, q, al20);
            s20 = s; q20 = q;
        }
        #pragma unroll
        for (int t = 0; t < 20; t++) __stcs(&op[t * Hc], ob[t]);
        tbeg = 20;
        // ring invariant: r[i] == x[i] == x[t-20] for t = 20+i ✓
    } else {
        // ---- halo warmup: ring <- x[t0-20 .. t0-1] ----
        const int t0 = chunk * TCc;
        const float* ph = xp + (size_t)(t0 - 20) * Hc;
        #pragma unroll
        for (int i = 0; i < 20; i++) r[i] = __ldg(&ph[i * Hc]);
        s5 = q5 = s10 = q10 = s20 = q20 = 0.f;
        #pragma unroll
        for (int i = 0; i < 20; i++) {
            float v = r[i], v2 = v * v;
            s20 += v; q20 += v2;
            if (i >= 10) { s10 += v; q10 += v2; }
            if (i >= 15) { s5  += v; q5  += v2; }
        }
        tbeg = t0;
    }

    const int tend = chunk * TCc + TCc;
    int tb = tbeg;

    // ---- steady state: 20-step blocks, compile-time ring indices ----
    for (; tb + 20 <= tend; tb += 20) {
        const float* p = xp + (size_t)tb * Hc;
        float*       o = op + (size_t)tb * Hc;
        float xv[10];
        #pragma unroll
        for (int j = 0; j < 10; j++) xv[j] = __ldg(&p[j * Hc]);
        STEP(0, xv[0], o); STEP(1, xv[1], o); STEP(2, xv[2], o); STEP(3, xv[3], o);
        STEP(4, xv[4], o); STEP(5, xv[5], o); STEP(6, xv[6], o); STEP(7, xv[7], o);
        STEP(8, xv[8], o); STEP(9, xv[9], o);
        #pragma unroll
        for (int j = 0; j < 10; j++) xv[j] = __ldg(&p[(j + 10) * Hc]);
        STEP(10, xv[0], o); STEP(11, xv[1], o); STEP(12, xv[2], o); STEP(13, xv[3], o);
        STEP(14, xv[4], o); STEP(15, xv[5], o); STEP(16, xv[6], o); STEP(17, xv[7], o);
        STEP(18, xv[8], o); STEP(19, xv[9], o);
    }

    // ---- fixed 8-step tail (ring base slot is 0 here) ----
    {
        const float* p = xp + (size_t)tb * Hc;
        float*       o = op + (size_t)tb * Hc;
        float xv[8];
        #pragma unroll
        for (int j = 0; j < 8; j++) xv[j] = __ldg(&p[j * Hc]);
        STEP(0, xv[0], o); STEP(1, xv[1], o); STEP(2, xv[2], o); STEP(3, xv[3], o);
        STEP(4, xv[4], o); STEP(5, xv[5], o); STEP(6, xv[6], o); STEP(7, xv[7], o);
    }
}

extern "C" void kernel_launch(void* const* d_in, const int* in_sizes, int n_in,
                              void* d_out, int out_size) {
    const float* x     = (const float*)d_in[0];
    const float* alpha = (const float*)d_in[1];
    float*       out   = (float*)d_out;
    dim3 grid(Bc * NHB * NCH);   // 32 * 8 * 16 = 4096 blocks
    dim3 block(HCc);             // 64 threads
    fan_kernel<<<grid, block>>>(x, alpha, out);
}

// round 10
// speedup vs baseline: 1.4519x; 1.1916x over previous
#include <cuda_runtime.h>
#include <cuda_bf16.h>

// FrequencyAdaptiveNormSimple: out = sum_w softmax(alpha)[h,w] * (x - mu_w)/max(sd_w,1e-4)
// windows (5,10,20), replicate-padded stats for t < w-1. B=32,T=2048,H=512 fp32.
// Cumulative-sum register ring: ring holds running (cs, cq); window sums are
// single subtractions against lag slots. Per-chunk reset bounds fp32 drift.

constexpr int Bc  = 32;
constexpr int Tc  = 2048;
constexpr int Hc  = 512;
constexpr int HCc = 64;           // h per block (= threads per block)
constexpr int TCc = 128;          // time chunk per block
constexpr int NCH = Tc / TCc;     // 16
constexpr int NHB = Hc / HCc;     // 8
static_assert(TCc % 20 == 8, "tail length assumed 8");

static __device__ __forceinline__ float rsq(float v) {
    float r;
    asm("rsqrt.approx.f32 %0, %1;" : "=f"(r) : "f"(v));
    return r;
}

// edge-path znorm (t < 20), plain form
template <int W>
static __device__ __forceinline__ float zc(float xv, float s, float q, float al) {
    const float c1   = 1.0f / (float)(W - 1);
    const float c2   = 1.0f / ((float)W * (float)(W - 1));
    const float invW = 1.0f / (float)W;
    float var   = q * c1 - (s * c2) * s;
    float invsd = rsq(fmaxf(var, 1e-8f));
    return (xv - s * invW) * (al * invsd);
}

// one steady-state timestep; J literal so ring indices are compile-time.
// ring slot k holds cumulative (cs, cq) for time (tb - 20 + k) until step k
// overwrites it with time (tb + k). Lags read before/after per the proof in
// the header comment of this round.
#define STEP(J, V, OPTR) {                                            \
    float _v    = (V);                                                \
    float _l20s = rcs[(J)];                 /* cs(t-20) */            \
    float _l20q = rcq[(J)];                                           \
    float _cs   = rcs[((J) + 19) % 20] + _v;                          \
    float _cq   = fmaf(_v, _v, rcq[((J) + 19) % 20]);                 \
    rcs[(J)] = _cs; rcq[(J)] = _cq;                                   \
    float _s20 = _cs - _l20s,              _q20 = _cq - _l20q;        \
    float _s10 = _cs - rcs[((J)+10)%20],   _q10 = _cq - rcq[((J)+10)%20]; \
    float _s5  = _cs - rcs[((J)+15)%20],   _q5  = _cq - rcq[((J)+15)%20]; \
    float _t5  = _s5  * -0.2f;                                        \
    float _t10 = _s10 * -0.1f;                                        \
    float _t20 = _s20 * -0.05f;                                       \
    float _m5  = _v + _t5,  _m10 = _v + _t10, _m20 = _v + _t20;       \
    float _v5  = fmaf(_t5,  _s5,  _q5);                               \
    float _v10 = fmaf(_t10, _s10, _q10);                              \
    float _v20 = fmaf(_t20, _s20, _q20);                              \
    float _w5  = a5  * rsq(fmaxf(_v5,  4e-8f));                       \
    float _w10 = a10 * rsq(fmaxf(_v10, 9e-8f));                       \
    float _w20 = a20 * rsq(fmaxf(_v20, 19e-8f));                      \
    float _o = fmaf(_m5, _w5, fmaf(_m10, _w10, _m20 * _w20));         \
    __stcs(&(OPTR)[(J) * Hc], _o); }

__global__ __launch_bounds__(HCc)
void fan_kernel(const float* __restrict__ x,
                const float* __restrict__ alpha,
                float* __restrict__ out)
{
    const int tid   = threadIdx.x;
    int blk         = blockIdx.x;
    const int chunk = blk % NCH; blk /= NCH;
    const int hb    = blk % NHB; blk /= NHB;
    const int b     = blk;
    const int h     = hb * HCc + tid;

    const float* xp = x   + (size_t)b * Tc * Hc + h;
    float*       op = out + (size_t)b * Tc * Hc + h;

    // per-feature softmax over 3 window weights
    float a0 = __ldg(&alpha[h * 3 + 0]);
    float a1 = __ldg(&alpha[h * 3 + 1]);
    float a2 = __ldg(&alpha[h * 3 + 2]);
    float mx = fmaxf(a0, fmaxf(a1, a2));
    float e0 = __expf(a0 - mx), e1 = __expf(a1 - mx), e2 = __expf(a2 - mx);
    float ai = 1.0f / (e0 + e1 + e2);
    const float al5 = e0 * ai, al10 = e1 * ai, al20 = e2 * ai;
    // steady-state weights with sqrt(W-1) folded in (var0 = (W-1)*var)
    const float a5  = al5  * 2.0f;            // sqrt(4)
    const float a10 = al10 * 3.0f;            // sqrt(9)
    const float a20 = al20 * 4.35889894354f;  // sqrt(19)

    float rcs[20], rcq[20];      // cumulative ring
    const float* ph;             // warmup source: 20 values ending at tbeg-1
    int tbeg;

    if (chunk == 0) {
        // ---- t = 0..19 with replicate-padded leading stats (raw scoped ring) ----
        {
            float r[20], ob[20];
            #pragma unroll
            for (int t = 0; t < 20; t++) { r[t] = __ldg(&xp[t * Hc]); ob[t] = 0.0f; }
            // w = 5
            {
                float s = 0.f, q = 0.f;
                #pragma unroll
                for (int t = 0; t < 20; t++) {
                    float v = r[t];
                    s += v; q += v * v;
                    if (t >= 5) { float l = r[t - 5]; s -= l; q -= l * l; }
                    if (t == 4) {
                        #pragma unroll
                        for (int tp = 0; tp <= 4; tp++) ob[tp] += zc<5>(r[tp], s, q, al5);
                    } else if (t > 4) {
                        ob[t] += zc<5>(v, s, q, al5);
                    }
                }
            }
            // w = 10
            {
                float s = 0.f, q = 0.f;
                #pragma unroll
                for (int t = 0; t < 20; t++) {
                    float v = r[t];
                    s += v; q += v * v;
                    if (t >= 10) { float l = r[t - 10]; s -= l; q -= l * l; }
                    if (t == 9) {
                        #pragma unroll
                        for (int tp = 0; tp <= 9; tp++) ob[tp] += zc<10>(r[tp], s, q, al10);
                    } else if (t > 9) {
                        ob[t] += zc<10>(v, s, q, al10);
                    }
                }
            }
            // w = 20
            {
                float s = 0.f, q = 0.f;
                #pragma unroll
                for (int t = 0; t < 20; t++) { float v = r[t]; s += v; q += v * v; }
                #pragma unroll
                for (int tp = 0; tp < 20; tp++) ob[tp] += zc<20>(r[tp], s, q, al20);
            }
            #pragma unroll
            for (int t = 0; t < 20; t++) __stcs(&op[t * Hc], ob[t]);
        }
        ph   = xp;          // warmup re-reads x[0..19] (L2-hot)
        tbeg = 20;
    } else {
        const int t0 = chunk * TCc;
        ph   = xp + (size_t)(t0 - 20) * Hc;
        tbeg = t0;
    }

    // ---- common warmup: build cumulative ring over the 20 warmup values ----
    {
        float cs = 0.f, cq = 0.f;
        #pragma unroll
        for (int i = 0; i < 20; i++) {
            float v = __ldg(&ph[i * Hc]);
            cs += v;
            cq  = fmaf(v, v, cq);
            rcs[i] = cs;
            rcq[i] = cq;
        }
    }

    const int tend = chunk * TCc + TCc;
    int tb = tbeg;

    // ---- steady state: 20-step blocks, compile-time ring indices ----
    for (; tb + 20 <= tend; tb += 20) {
        const float* p = xp + (size_t)tb * Hc;
        float*       o = op + (size_t)tb * Hc;
        float xv[5];
        #pragma unroll
        for (int j = 0; j < 5; j++) xv[j] = __ldg(&p[j * Hc]);
        STEP(0, xv[0], o); STEP(1, xv[1], o); STEP(2, xv[2], o);
        STEP(3, xv[3], o); STEP(4, xv[4], o);
        #pragma unroll
        for (int j = 0; j < 5; j++) xv[j] = __ldg(&p[(j + 5) * Hc]);
        STEP(5, xv[0], o); STEP(6, xv[1], o); STEP(7, xv[2], o);
        STEP(8, xv[3], o); STEP(9, xv[4], o);
        #pragma unroll
        for (int j = 0; j < 5; j++) xv[j] = __ldg(&p[(j + 10) * Hc]);
        STEP(10, xv[0], o); STEP(11, xv[1], o); STEP(12, xv[2], o);
        STEP(13, xv[3], o); STEP(14, xv[4], o);
        #pragma unroll
        for (int j = 0; j < 5; j++) xv[j] = __ldg(&p[(j + 15) * Hc]);
        STEP(15, xv[0], o); STEP(16, xv[1], o); STEP(17, xv[2], o);
        STEP(18, xv[3], o); STEP(19, xv[4], o);
    }

    // ---- fixed 8-step tail (ring phase is 0 mod 20 here) ----
    {
        const float* p = xp + (size_t)tb * Hc;
        float*       o = op + (size_t)tb * Hc;
        float xv[4];
        #pragma unroll
        for (int j = 0; j < 4; j++) xv[j] = __ldg(&p[j * Hc]);
        STEP(0, xv[0], o); STEP(1, xv[1], o); STEP(2, xv[2], o); STEP(3, xv[3], o);
        #pragma unroll
        for (int j = 0; j < 4; j++) xv[j] = __ldg(&p[(j + 4) * Hc]);
        STEP(4, xv[0], o); STEP(5, xv[1], o); STEP(6, xv[2], o); STEP(7, xv[3], o);
    }
}

extern "C" void kernel_launch(void* const* d_in, const int* in_sizes, int n_in,
                              void* d_out, int out_size) {
    const float* x     = (const float*)d_in[0];
    const float* alpha = (const float*)d_in[1];
    float*       out   = (float*)d_out;
    dim3 grid(Bc * NHB * NCH);   // 32 * 8 * 16 = 4096 blocks
    dim3 block(HCc);             // 64 threads
    fan_kernel<<<grid, block>>>(x, alpha, out);
}

// round 11
// speedup vs baseline: 1.4629x; 1.0076x over previous
#include <cuda_runtime.h>
#include <cuda_bf16.h>

// FrequencyAdaptiveNormSimple: out = sum_w softmax(alpha)[h,w] * (x - mu_w)/max(sd_w,1e-4)
// windows (5,10,20), replicate-padded stats for t < w-1. B=32,T=2048,H=512 fp32.
// Cumulative-sum register ring + software-pipelined (double-buffered) loads:
// next 5-step batch is fetched before the current batch's compute, hiding
// L2/DRAM latency inside each warp instead of relying on occupancy.

constexpr int Bc  = 32;
constexpr int Tc  = 2048;
constexpr int Hc  = 512;
constexpr int HCc = 64;           // h per block (= threads per block)
constexpr int TCc = 128;          // time chunk per block
constexpr int NCH = Tc / TCc;     // 16
constexpr int NHB = Hc / HCc;     // 8
static_assert(TCc % 20 == 8, "tail length assumed 8");

static __device__ __forceinline__ float rsq(float v) {
    float r;
    asm("rsqrt.approx.f32 %0, %1;" : "=f"(r) : "f"(v));
    return r;
}

// edge-path znorm (t < 20), plain form
template <int W>
static __device__ __forceinline__ float zc(float xv, float s, float q, float al) {
    const float c1   = 1.0f / (float)(W - 1);
    const float c2   = 1.0f / ((float)W * (float)(W - 1));
    const float invW = 1.0f / (float)W;
    float var   = q * c1 - (s * c2) * s;
    float invsd = rsq(fmaxf(var, 1e-8f));
    return (xv - s * invW) * (al * invsd);
}

// one steady-state timestep; J literal so ring indices are compile-time.
// ring slot k holds cumulative (cs, cq) of time (tb-20+k) until step k
// overwrites it with time (tb+k).
#define STEP(J, V, OPTR) {                                            \
    float _v    = (V);                                                \
    float _l20s = rcs[(J)];                 /* cs(t-20) */            \
    float _l20q = rcq[(J)];                                           \
    float _cs   = rcs[((J) + 19) % 20] + _v;                          \
    float _cq   = fmaf(_v, _v, rcq[((J) + 19) % 20]);                 \
    rcs[(J)] = _cs; rcq[(J)] = _cq;                                   \
    float _s20 = _cs - _l20s,              _q20 = _cq - _l20q;        \
    float _s10 = _cs - rcs[((J)+10)%20],   _q10 = _cq - rcq[((J)+10)%20]; \
    float _s5  = _cs - rcs[((J)+15)%20],   _q5  = _cq - rcq[((J)+15)%20]; \
    float _t5  = _s5  * -0.2f;                                        \
    float _t10 = _s10 * -0.1f;                                        \
    float _t20 = _s20 * -0.05f;                                       \
    float _m5  = _v + _t5,  _m10 = _v + _t10, _m20 = _v + _t20;       \
    float _v5  = fmaf(_t5,  _s5,  _q5);                               \
    float _v10 = fmaf(_t10, _s10, _q10);                              \
    float _v20 = fmaf(_t20, _s20, _q20);                              \
    float _w5  = a5  * rsq(fmaxf(_v5,  4e-8f));                       \
    float _w10 = a10 * rsq(fmaxf(_v10, 9e-8f));                       \
    float _w20 = a20 * rsq(fmaxf(_v20, 19e-8f));                      \
    float _o = fmaf(_m5, _w5, fmaf(_m10, _w10, _m20 * _w20));         \
    __stcs(&(OPTR)[(J) * Hc], _o); }

#define LOAD5(DST, P, OFF)                                  \
    { _Pragma("unroll")                                     \
      for (int _j = 0; _j < 5; _j++)                        \
          (DST)[_j] = __ldg(&(P)[((OFF) + _j) * Hc]); }

__global__ __launch_bounds__(HCc)
void fan_kernel(const float* __restrict__ x,
                const float* __restrict__ alpha,
                float* __restrict__ out)
{
    const int tid   = threadIdx.x;
    int blk         = blockIdx.x;
    const int chunk = blk % NCH; blk /= NCH;
    const int hb    = blk % NHB; blk /= NHB;
    const int b     = blk;
    const int h     = hb * HCc + tid;

    const float* xp = x   + (size_t)b * Tc * Hc + h;
    float*       op = out + (size_t)b * Tc * Hc + h;

    // per-feature softmax over 3 window weights
    float a0 = __ldg(&alpha[h * 3 + 0]);
    float a1 = __ldg(&alpha[h * 3 + 1]);
    float a2 = __ldg(&alpha[h * 3 + 2]);
    float mx = fmaxf(a0, fmaxf(a1, a2));
    float e0 = __expf(a0 - mx), e1 = __expf(a1 - mx), e2 = __expf(a2 - mx);
    float ai = 1.0f / (e0 + e1 + e2);
    const float al5 = e0 * ai, al10 = e1 * ai, al20 = e2 * ai;
    // steady-state weights with sqrt(W-1) folded in (var0 = (W-1)*var)
    const float a5  = al5  * 2.0f;            // sqrt(4)
    const float a10 = al10 * 3.0f;            // sqrt(9)
    const float a20 = al20 * 4.35889894354f;  // sqrt(19)

    float rcs[20], rcq[20];      // cumulative ring
    const float* ph;             // warmup source: 20 values ending at tbeg-1
    int tbeg;

    if (chunk == 0) {
        // ---- t = 0..19 with replicate-padded leading stats (raw scoped ring) ----
        {
            float r[20], ob[20];
            #pragma unroll
            for (int t = 0; t < 20; t++) { r[t] = __ldg(&xp[t * Hc]); ob[t] = 0.0f; }
            // w = 5
            {
                float s = 0.f, q = 0.f;
                #pragma unroll
                for (int t = 0; t < 20; t++) {
                    float v = r[t];
                    s += v; q += v * v;
                    if (t >= 5) { float l = r[t - 5]; s -= l; q -= l * l; }
                    if (t == 4) {
                        #pragma unroll
                        for (int tp = 0; tp <= 4; tp++) ob[tp] += zc<5>(r[tp], s, q, al5);
                    } else if (t > 4) {
                        ob[t] += zc<5>(v, s, q, al5);
                    }
                }
            }
            // w = 10
            {
                float s = 0.f, q = 0.f;
                #pragma unroll
                for (int t = 0; t < 20; t++) {
                    float v = r[t];
                    s += v; q += v * v;
                    if (t >= 10) { float l = r[t - 10]; s -= l; q -= l * l; }
                    if (t == 9) {
                        #pragma unroll
                        for (int tp = 0; tp <= 9; tp++) ob[tp] += zc<10>(r[tp], s, q, al10);
                    } else if (t > 9) {
                        ob[t] += zc<10>(v, s, q, al10);
                    }
                }
            }
            // w = 20
            {
                float s = 0.f, q = 0.f;
                #pragma unroll
                for (int t = 0; t < 20; t++) { float v = r[t]; s += v; q += v * v; }
                #pragma unroll
                for (int tp = 0; tp < 20; tp++) ob[tp] += zc<20>(r[tp], s, q, al20);
            }
            #pragma unroll
            for (int t = 0; t < 20; t++) __stcs(&op[t * Hc], ob[t]);
        }
        ph   = xp;          // warmup re-reads x[0..19] (L2-hot)
        tbeg = 20;
    } else {
        const int t0 = chunk * TCc;
        ph   = xp + (size_t)(t0 - 20) * Hc;
        tbeg = t0;
    }

    // ---- common warmup: build cumulative ring over the 20 warmup values ----
    {
        float cs = 0.f, cq = 0.f;
        #pragma unroll
        for (int i = 0; i < 20; i++) {
            float v = __ldg(&ph[i * Hc]);
            cs += v;
            cq  = fmaf(v, v, cq);
            rcs[i] = cs;
            rcq[i] = cq;
        }
    }

    const int tend = chunk * TCc + TCc;
    int tb = tbeg;

    // ---- steady state: 20-step blocks, double-buffered 5-wide load batches.
    // Prefetch of the next group is issued BEFORE the current group's compute.
    // The last in-loop prefetch (p[20..24]) lands on tail steps 0..4, which
    // always exist (tail = 8 >= 5), so it never reads out of bounds.
    float xa[5], xb[5];
    {
        const float* p0 = xp + (size_t)tb * Hc;
        LOAD5(xa, p0, 0);
    }
    #pragma unroll 1
    for (; tb + 20 <= tend; tb += 20) {
        const float* p = xp + (size_t)tb * Hc;
        float*       o = op + (size_t)tb * Hc;
        LOAD5(xb, p, 5);
        STEP(0, xa[0], o); STEP(1, xa[1], o); STEP(2, xa[2], o);
        STEP(3, xa[3], o); STEP(4, xa[4], o);
        LOAD5(xa, p, 10);
        STEP(5, xb[0], o); STEP(6, xb[1], o); STEP(7, xb[2], o);
        STEP(8, xb[3], o); STEP(9, xb[4], o);
        LOAD5(xb, p, 15);
        STEP(10, xa[0], o); STEP(11, xa[1], o); STEP(12, xa[2], o);
        STEP(13, xa[3], o); STEP(14, xa[4], o);
        LOAD5(xa, p, 20);   // next block (or tail steps 0..4 on last iter)
        STEP(15, xb[0], o); STEP(16, xb[1], o); STEP(17, xb[2], o);
        STEP(18, xb[3], o); STEP(19, xb[4], o);
    }

    // ---- fixed 8-step tail (ring phase 0; xa holds tail steps 0..4) ----
    {
        const float* p = xp + (size_t)tb * Hc;
        float*       o = op + (size_t)tb * Hc;
        float xc[3];
        #pragma unroll
        for (int j = 0; j < 3; j++) xc[j] = __ldg(&p[(5 + j) * Hc]);
        STEP(0, xa[0], o); STEP(1, xa[1], o); STEP(2, xa[2], o);
        STEP(3, xa[3], o); STEP(4, xa[4], o);
        STEP(5, xc[0], o); STEP(6, xc[1], o); STEP(7, xc[2], o);
    }
}

extern "C" void kernel_launch(void* const* d_in, const int* in_sizes, int n_in,
                              void* d_out, int out_size) {
    const float* x     = (const float*)d_in[0];
    const float* alpha = (const float*)d_in[1];
    float*       out   = (float*)d_out;
    dim3 grid(Bc * NHB * NCH);   // 32 * 8 * 16 = 4096 blocks
    dim3 block(HCc);             // 64 threads
    fan_kernel<<<grid, block>>>(x, alpha, out);
}